// round 6
// baseline (speedup 1.0000x reference)
#include <cuda_runtime.h>

// CRF forward (log-partition) + Viterbi decode, fused.
// Dual-batch per CTA: grid=256, 96 threads, each thread runs state s for TWO
// independent batches (in-thread ILP hides the recurrence latency).
// Thread map: lane = 2*(s%16)+h, h in {0,1} handles 24 prev-states.
// Lagged scalar normalizer (alpha[state 0]) + double-buffered publish =>
// ONE __syncthreads per step for both batches. f32x2 packed dot/adds.
// Parallel chunked backtrace for both batches.
//
// Output layout (float32): [logz(B) | scores(B) | paths(B*T)]

#define Bc 512
#define Tc 1024
#define Kc 48
#define START_T 46
#define END_T 47
#define NEGV (-10000.0f)

#define OFF_BP    0                         // [2][T][48] uint8 = 98304
#define OFF_W     (2*Tc*Kc)                 // [2 batch][2 buf][48] float = 768
#define OFF_V     (OFF_W + 2*2*Kc*4)        // 768
#define OFF_RED   (OFF_V + 2*2*Kc*4)        // [2 batch][2 buf] float = 16
#define OFF_AFIN  (OFF_RED + 16)            // [2][48] float = 384
#define OFF_VFIN  (OFF_AFIN + 2*Kc*4)       // 384
#define OFF_MC    (OFF_VFIN + 2*Kc*4)       // [2][64][48] uchar = 6144
#define OFF_EC    (OFF_MC + 2*64*Kc)        // [2][64] uchar = 128
#define OFF_LAST  (OFF_EC + 128)            // [2] int
#define SMEM_TOTAL (OFF_LAST + 16)

typedef unsigned long long u64;

__device__ __forceinline__ float ninf() { return __int_as_float(0xff800000); }
__device__ __forceinline__ u64 pk2(float lo, float hi) {
    u64 r; asm("mov.b64 %0,{%1,%2};" : "=l"(r) : "f"(lo), "f"(hi)); return r;
}
__device__ __forceinline__ void upk2(u64 x, float& lo, float& hi) {
    asm("mov.b64 {%0,%1},%2;" : "=f"(lo), "=f"(hi) : "l"(x));
}
__device__ __forceinline__ u64 fma2(u64 a, u64 b, u64 c) {
    u64 d; asm("fma.rn.f32x2 %0,%1,%2,%3;" : "=l"(d) : "l"(a), "l"(b), "l"(c)); return d;
}
__device__ __forceinline__ u64 add2(u64 a, u64 b) {
    u64 d; asm("add.rn.f32x2 %0,%1,%2;" : "=l"(d) : "l"(a), "l"(b)); return d;
}

__global__ void __launch_bounds__(96, 2)
crf_fused_kernel(const float* __restrict__ feats,
                 const float* __restrict__ trans,
                 float* __restrict__ out)
{
    extern __shared__ unsigned char smem[];
    unsigned char* bp0   = smem + OFF_BP;
    float* wp    = (float*)(smem + OFF_W);     // [(bt*2+buf)*48 + s]
    float* vp    = (float*)(smem + OFF_V);
    float* red   = (float*)(smem + OFF_RED);   // [bt*2+buf]
    float* a_fin = (float*)(smem + OFF_AFIN);
    float* v_fin = (float*)(smem + OFF_VFIN);
    unsigned char* Mc = smem + OFF_MC;
    unsigned char* Ec = smem + OFF_EC;
    int* lastp = (int*)(smem + OFF_LAST);

    const int tid  = threadIdx.x;
    const int lane = tid & 31;
    const int wz   = tid >> 5;
    const int s    = wz * 16 + (lane >> 1);
    const int h    = lane & 1;
    const int pbase = h * 24;

    // Masked transition slice, packed in f32x2 pairs: p in [pbase, pbase+24)
    u64 TR2[12], E2[12];
#pragma unroll
    for (int j = 0; j < 12; j++) {
        int p0 = pbase + 2 * j, p1 = p0 + 1;
        float t0 = trans[s * Kc + p0];
        float t1 = trans[s * Kc + p1];
        if (s == START_T) { t0 = NEGV; t1 = NEGV; }
        if (p0 == END_T) t0 = NEGV;
        if (p1 == END_T) t1 = NEGV;
        TR2[j] = pk2(t0, t1);
        E2[j]  = pk2(__expf(t0), __expf(t1));   // exp(-10000) == 0.0f exactly
    }

    if (tid < 4) red[tid] = 0.f;

    float al[2], vv[2], mc[2], fA[2], fB[2];
    const float* fb[2];
#pragma unroll
    for (int bt = 0; bt < 2; bt++) {
        al[bt] = (s == START_T) ? 0.0f : NEGV;
        vv[bt] = al[bt];
        mc[bt] = 0.0f;
        fb[bt] = feats + (size_t)(2 * blockIdx.x + bt) * Tc * Kc + s;
        fA[bt] = (h == 0) ? fb[bt][0]  : 0.f;
        fB[bt] = (h == 0) ? fb[bt][Kc] : 0.f;
    }

    for (int t = 0; t < Tc; t++) {
        const int buf = t & 1;
#pragma unroll
        for (int bt = 0; bt < 2; bt++) {
            if (h == 0) {
                wp[(bt * 2 + buf) * Kc + s] = __expf(al[bt] - mc[bt]); // -inf -> 0
                vp[(bt * 2 + buf) * Kc + s] = vv[bt];
            }
        }
        const int tp = (t + 2 < Tc) ? (t + 2) : t;   // prefetch (dummy at tail)
        float fC[2];
#pragma unroll
        for (int bt = 0; bt < 2; bt++)
            fC[bt] = (h == 0) ? fb[bt][tp * Kc] : 0.f;

        __syncthreads();
        float mn[2];
#pragma unroll
        for (int bt = 0; bt < 2; bt++) mn[bt] = red[bt * 2 + (1 - buf)];

        u64 aP[2] = {0ull, 0ull}, aQ[2] = {0ull, 0ull};
        float cb0[2] = {ninf(), ninf()}, cb1[2] = {ninf(), ninf()};
        int   ci0[2] = {0, 0},           ci1[2] = {0, 0};
        const ulonglong2* wq4[2];
        const ulonglong2* vq4[2];
#pragma unroll
        for (int bt = 0; bt < 2; bt++) {
            wq4[bt] = (const ulonglong2*)(wp + (bt * 2 + buf) * Kc) + h * 6;
            vq4[bt] = (const ulonglong2*)(vp + (bt * 2 + buf) * Kc) + h * 6;
        }

#pragma unroll
        for (int jj = 0; jj < 6; jj++) {
#pragma unroll
            for (int bt = 0; bt < 2; bt++) {
                ulonglong2 wq = wq4[bt][jj];
                ulonglong2 vq = vq4[bt][jj];
                aP[bt] = fma2(wq.x, E2[2 * jj],     aP[bt]);
                aQ[bt] = fma2(wq.y, E2[2 * jj + 1], aQ[bt]);
                u64 c01 = add2(vq.x, TR2[2 * jj]);
                u64 c23 = add2(vq.y, TR2[2 * jj + 1]);
                float s0, s1, s2, s3;
                upk2(c01, s0, s1);
                upk2(c23, s2, s3);
                if (jj < 3) {   // local cands 0..11 (contiguous => strict '>')
                    if (s0 > cb0[bt]) { cb0[bt] = s0; ci0[bt] = 4 * jj + 0; }
                    if (s1 > cb0[bt]) { cb0[bt] = s1; ci0[bt] = 4 * jj + 1; }
                    if (s2 > cb0[bt]) { cb0[bt] = s2; ci0[bt] = 4 * jj + 2; }
                    if (s3 > cb0[bt]) { cb0[bt] = s3; ci0[bt] = 4 * jj + 3; }
                } else {        // local cands 12..23
                    if (s0 > cb1[bt]) { cb1[bt] = s0; ci1[bt] = 4 * jj + 0; }
                    if (s1 > cb1[bt]) { cb1[bt] = s1; ci1[bt] = 4 * jj + 1; }
                    if (s2 > cb1[bt]) { cb1[bt] = s2; ci1[bt] = 4 * jj + 2; }
                    if (s3 > cb1[bt]) { cb1[bt] = s3; ci1[bt] = 4 * jj + 3; }
                }
            }
        }

#pragma unroll
        for (int bt = 0; bt < 2; bt++) {
            float best = cb0[bt]; int li = ci0[bt];
            if (cb1[bt] > best) { best = cb1[bt]; li = ci1[bt]; }
            int bi = pbase + li;

            float x0, x1, x2, x3;
            upk2(aP[bt], x0, x1);
            upk2(aQ[bt], x2, x3);
            float S = (x0 + x1) + (x2 + x3);
            S += __shfl_xor_sync(0xffffffffu, S, 1);
            float ob = __shfl_xor_sync(0xffffffffu, best, 1);
            int   oi = __shfl_xor_sync(0xffffffffu, bi, 1);
            if (ob > best || (ob == best && oi < bi)) { best = ob; bi = oi; }

            if (h == 0) {
                al[bt] = mc[bt] + __logf(S) + fA[bt];  // log(0)->-inf only START
                vv[bt] = best + fA[bt];
                (bp0 + bt * Tc * Kc)[t * Kc + s] = (unsigned char)bi;
                if (s == 0) red[bt * 2 + buf] = al[bt];
            }
            mc[bt] = mn[bt];
            fA[bt] = fB[bt];
            fB[bt] = fC[bt];
        }
    }

    __syncthreads();
    if (h == 0) {
#pragma unroll
        for (int bt = 0; bt < 2; bt++) {
            a_fin[bt * Kc + s] = al[bt];
            v_fin[bt * Kc + s] = vv[bt];
        }
    }
    __syncthreads();

    // Termination: one thread per batch (different warps run in parallel)
    if ((tid & 31) == 0 && tid < 64) {
        const int bt = tid >> 5;
        const int b  = 2 * blockIdx.x + bt;
        float mx = ninf();
#pragma unroll
        for (int p = 0; p < Kc; p++) {
            float te = (p == END_T) ? NEGV : trans[END_T * Kc + p];
            mx = fmaxf(mx, a_fin[bt * Kc + p] + te);
        }
        float sum = 0.f;
#pragma unroll
        for (int p = 0; p < Kc; p++) {
            float te = (p == END_T) ? NEGV : trans[END_T * Kc + p];
            sum += __expf((a_fin[bt * Kc + p] + te) - mx);
        }
        float logz = mx + __logf(sum);

        float bestT = ninf(); int last = 0;
#pragma unroll
        for (int p = 0; p < Kc; p++) {
            float te = (p == END_T) ? NEGV : trans[END_T * Kc + p];
            float tm = v_fin[bt * Kc + p] + te;
            if (tm > bestT) { bestT = tm; last = p; }
        }
        out[b]      = logz;
        out[Bc + b] = bestT;
        lastp[bt] = last;
    }
    __syncthreads();

    // ---- Parallel backtrace: 2 batches x 64 chunks of 16 steps ----
    // Phase A: Mc[bb][c][e] = tag after walking chunk c of batch bb from entry e.
    for (int ct = tid; ct < 128; ct += 96) {
        const int bb = ct >> 6;
        const int c  = ct & 63;
        const unsigned char* bpb = bp0 + bb * Tc * Kc;
        for (int half = 0; half < 2; half++) {
            unsigned char tg[24];
#pragma unroll
            for (int e = 0; e < 24; e++) tg[e] = (unsigned char)(half * 24 + e);
            for (int i = 15; i >= 0; i--) {
                const unsigned char* row = bpb + (c * 16 + i) * Kc;
#pragma unroll
                for (int e = 0; e < 24; e++) tg[e] = row[tg[e]];
            }
#pragma unroll
            for (int e = 0; e < 24; e++) Mc[(bb * 64 + c) * Kc + half * 24 + e] = tg[e];
        }
    }
    __syncthreads();
    // Phase B: serial chain over 64 chunks, one thread per batch
    if ((tid & 31) == 0 && tid < 64) {
        const int bb = tid >> 5;
        int tag = lastp[bb];
        for (int c = 63; c >= 0; c--) {
            Ec[bb * 64 + c] = (unsigned char)tag;
            tag = Mc[(bb * 64 + c) * Kc + tag];
        }
    }
    __syncthreads();
    // Phase C: emit 16 path entries per chunk-task
    for (int ct = tid; ct < 128; ct += 96) {
        const int bb = ct >> 6;
        const int c  = ct & 63;
        const unsigned char* bpb = bp0 + bb * Tc * Kc;
        float* pout = out + 2 * Bc + (size_t)(2 * blockIdx.x + bb) * Tc + c * 16;
        int tg = Ec[bb * 64 + c];
        for (int i = 15; i >= 0; i--) {
            pout[i] = (float)tg;
            tg = bpb[(c * 16 + i) * Kc + tg];
        }
    }
}

extern "C" void kernel_launch(void* const* d_in, const int* in_sizes, int n_in,
                              void* d_out, int out_size)
{
    (void)in_sizes; (void)n_in; (void)out_size;
    const float* feats = (const float*)d_in[0];
    const float* trans = (const float*)d_in[1];
    float* out = (float*)d_out;

    cudaFuncSetAttribute(crf_fused_kernel,
                         cudaFuncAttributeMaxDynamicSharedMemorySize, SMEM_TOTAL);
    crf_fused_kernel<<<Bc / 2, 96, SMEM_TOTAL>>>(feats, trans, out);
}

// round 11
// speedup vs baseline: 1.3562x; 1.3562x over previous
#include <cuda_runtime.h>

// CRF forward (log-partition) + Viterbi decode with ROLE-SPLIT warp groups.
// One CTA per batch, 160 threads:
//   threads 0-63   (warps 0-1): forward recurrence, 1 thread per state,
//                               full 48-wide dot in registers (no shfl).
//   threads 64-159 (warps 2-4): viterbi recurrence, 2 threads per state
//                               (24 prev-candidates each, shfl_xor(1) merge).
// Each group syncs with its own named barrier => the two recurrences run
// fully asynchronously. Lagged scalar normalizer (alpha[state 0]).
// Double-buffered publish => ONE barrier per step per group.
//
// Output layout (float32): [logz(B) | scores(B) | paths(B*T)]

#define Bc 512
#define Tc 1024
#define Kc 48
#define START_T 46
#define END_T 47
#define NEGV (-10000.0f)

#define OFF_BP    0                         // [T][48] uint8 = 49152
#define OFF_W     (Tc*Kc)                   // [2][48] float = 384
#define OFF_V     (OFF_W + 2*Kc*4)          // 384
#define OFF_RED   (OFF_V + 2*Kc*4)          // 2 floats (+pad)
#define OFF_AFIN  (OFF_RED + 16)            // 192
#define OFF_VFIN  (OFF_AFIN + Kc*4)         // 192
#define OFF_MC    (OFF_VFIN + Kc*4)         // 64*48 = 3072
#define OFF_EC    (OFF_MC + 64*Kc)          // 64
#define OFF_LAST  (OFF_EC + 64)             // 4
#define SMEM_TOTAL (OFF_LAST + 16)          // ~53.5 KB

typedef unsigned long long u64;

__device__ __forceinline__ float ninf() { return __int_as_float(0xff800000); }
__device__ __forceinline__ u64 pk2(float lo, float hi) {
    u64 r; asm("mov.b64 %0,{%1,%2};" : "=l"(r) : "f"(lo), "f"(hi)); return r;
}
__device__ __forceinline__ void upk2(u64 x, float& lo, float& hi) {
    asm("mov.b64 {%0,%1},%2;" : "=f"(lo), "=f"(hi) : "l"(x));
}
__device__ __forceinline__ u64 fma2(u64 a, u64 b, u64 c) {
    u64 d; asm("fma.rn.f32x2 %0,%1,%2,%3;" : "=l"(d) : "l"(a), "l"(b), "l"(c)); return d;
}
__device__ __forceinline__ u64 add2(u64 a, u64 b) {
    u64 d; asm("add.rn.f32x2 %0,%1,%2;" : "=l"(d) : "l"(a), "l"(b)); return d;
}

__global__ void __launch_bounds__(160, 4)
crf_fused_kernel(const float* __restrict__ feats,
                 const float* __restrict__ trans,
                 float* __restrict__ out)
{
    extern __shared__ unsigned char smem[];
    unsigned char* bptr = smem + OFF_BP;
    float* wp    = (float*)(smem + OFF_W);     // [buf][48] exp-weights
    float* vp    = (float*)(smem + OFF_V);     // [buf][48] viterbi values
    float* red   = (float*)(smem + OFF_RED);   // [buf] alpha[state 0]
    float* a_fin = (float*)(smem + OFF_AFIN);
    float* v_fin = (float*)(smem + OFF_VFIN);
    unsigned char* Mc = smem + OFF_MC;
    unsigned char* Ec = smem + OFF_EC;
    int* lastp = (int*)(smem + OFF_LAST);

    const int b   = blockIdx.x;
    const int tid = threadIdx.x;

    if (tid < 2) red[tid] = 0.f;
    __syncthreads();

    if (tid < 64) {
        // ================= FORWARD group (warps 0-1) =================
        const int s = tid;
        const bool act = (s < Kc);
        const int ss = act ? s : 0;

        u64 E2[24];                                // exp(masked trans row)
#pragma unroll
        for (int j = 0; j < 24; j++) {
            int p0 = 2 * j, p1 = 2 * j + 1;
            float t0 = trans[ss * Kc + p0];
            float t1 = trans[ss * Kc + p1];
            if (ss == START_T) { t0 = NEGV; t1 = NEGV; }
            if (p0 == END_T) t0 = NEGV;
            if (p1 == END_T) t1 = NEGV;
            E2[j] = pk2(__expf(t0), __expf(t1));   // exp(-10000) == 0 exactly
        }

        float al = (s == START_T) ? 0.f : NEGV;
        float mc = 0.f;
        const float* fbp = feats + (size_t)b * Tc * Kc + ss;
        float fA = fbp[0], fB = fbp[Kc];

        for (int t = 0; t < Tc; t++) {
            const int buf = t & 1;
            if (act) wp[buf * Kc + s] = __expf(al - mc);   // -inf -> 0 (safe)
            const int tp = (t + 2 < Tc) ? (t + 2) : t;
            float fC = fbp[tp * Kc];

            asm volatile("bar.sync 1, 64;" ::: "memory");
            float mn = red[1 - buf];

            const ulonglong2* w4 = (const ulonglong2*)(wp + buf * Kc);
            u64 P = 0ull, Q = 0ull;
#pragma unroll
            for (int j = 0; j < 12; j++) {
                ulonglong2 q = w4[j];
                P = fma2(q.x, E2[2 * j],     P);
                Q = fma2(q.y, E2[2 * j + 1], Q);
            }
            float x0, x1, x2, x3;
            upk2(P, x0, x1);
            upk2(Q, x2, x3);
            float S = (x0 + x1) + (x2 + x3);
            if (act) {
                al = mc + __logf(S) + fA;          // log(0)->-inf only START row
                if (s == 0) red[buf] = al;
            }
            mc = mn; fA = fB; fB = fC;
        }
        if (act) a_fin[s] = al;
    } else {
        // ================= VITERBI group (warps 2-4) =================
        const int r    = tid - 64;
        const int lane = r & 31;
        const int wz   = r >> 5;
        const int s    = wz * 16 + (lane >> 1);
        const int h    = lane & 1;
        const int pbase = h * 24;

        u64 TR2[12];                               // masked trans slice
#pragma unroll
        for (int j = 0; j < 12; j++) {
            int p0 = pbase + 2 * j, p1 = p0 + 1;
            float t0 = trans[s * Kc + p0];
            float t1 = trans[s * Kc + p1];
            if (s == START_T) { t0 = NEGV; t1 = NEGV; }
            if (p0 == END_T) t0 = NEGV;
            if (p1 == END_T) t1 = NEGV;
            TR2[j] = pk2(t0, t1);
        }

        float v = (s == START_T) ? 0.f : NEGV;
        const float* fbp = feats + (size_t)b * Tc * Kc + s;
        float fA = fbp[0], fB = fbp[Kc];

        for (int t = 0; t < Tc; t++) {
            const int buf = t & 1;
            if (h == 0) vp[buf * Kc + s] = v;
            const int tp = (t + 2 < Tc) ? (t + 2) : t;
            float fC = fbp[tp * Kc];

            asm volatile("bar.sync 2, 96;" ::: "memory");

            const ulonglong2* v4 = (const ulonglong2*)(vp + buf * Kc) + h * 6;
            float b0 = ninf(), b1 = ninf(), b2 = ninf();
            int   i0 = 0, i1 = 0, i2 = 0;
#pragma unroll
            for (int j = 0; j < 6; j++) {
                ulonglong2 q = v4[j];
                u64 c01 = add2(q.x, TR2[2 * j]);
                u64 c23 = add2(q.y, TR2[2 * j + 1]);
                float s0, s1, s2, s3;
                upk2(c01, s0, s1);
                upk2(c23, s2, s3);
                if (j < 2) {          // local cands 0..7 (ascending => strict '>')
                    if (s0 > b0) { b0 = s0; i0 = 4 * j + 0; }
                    if (s1 > b0) { b0 = s1; i0 = 4 * j + 1; }
                    if (s2 > b0) { b0 = s2; i0 = 4 * j + 2; }
                    if (s3 > b0) { b0 = s3; i0 = 4 * j + 3; }
                } else if (j < 4) {   // 8..15
                    if (s0 > b1) { b1 = s0; i1 = 4 * j + 0; }
                    if (s1 > b1) { b1 = s1; i1 = 4 * j + 1; }
                    if (s2 > b1) { b1 = s2; i1 = 4 * j + 2; }
                    if (s3 > b1) { b1 = s3; i1 = 4 * j + 3; }
                } else {              // 16..23
                    if (s0 > b2) { b2 = s0; i2 = 4 * j + 0; }
                    if (s1 > b2) { b2 = s1; i2 = 4 * j + 1; }
                    if (s2 > b2) { b2 = s2; i2 = 4 * j + 2; }
                    if (s3 > b2) { b2 = s3; i2 = 4 * j + 3; }
                }
            }
            float best = b0; int li = i0;
            if (b1 > best) { best = b1; li = i1; }
            if (b2 > best) { best = b2; li = i2; }
            int bi = pbase + li;

            float ob = __shfl_xor_sync(0xffffffffu, best, 1);
            int   oi = __shfl_xor_sync(0xffffffffu, bi, 1);
            // For the h==0 consumer, partner indices (24..47) are always larger,
            // so strict '>' preserves first-occurrence ties.
            if (ob > best) { best = ob; bi = oi; }

            if (h == 0) {
                v = best + fA;
                bptr[t * Kc + s] = (unsigned char)bi;
            }
            fA = fB; fB = fC;
        }
        if (h == 0) v_fin[s] = v;
    }

    __syncthreads();

    // Termination: tid 0 -> logz ; tid 64 -> viterbi terminal (parallel warps)
    if (tid == 0) {
        float mx = ninf();
#pragma unroll
        for (int p = 0; p < Kc; p++) {
            float te = (p == END_T) ? NEGV : trans[END_T * Kc + p];
            mx = fmaxf(mx, a_fin[p] + te);
        }
        float sum = 0.f;
#pragma unroll
        for (int p = 0; p < Kc; p++) {
            float te = (p == END_T) ? NEGV : trans[END_T * Kc + p];
            sum += __expf((a_fin[p] + te) - mx);
        }
        out[b] = mx + __logf(sum);
    }
    if (tid == 64) {
        float bestT = ninf(); int last = 0;
#pragma unroll
        for (int p = 0; p < Kc; p++) {
            float te = (p == END_T) ? NEGV : trans[END_T * Kc + p];
            float tm = v_fin[p] + te;
            if (tm > bestT) { bestT = tm; last = p; }
        }
        out[Bc + b] = bestT;
        *lastp = last;
    }
    __syncthreads();

    // ---- Parallel backtrace: 64 chunks of 16 steps ----
    // Phase A: 128 tasks (chunk c, half) -> Mc[c][e] = exit tag from entry e.
    if (tid < 128) {
        const int c    = tid >> 1;
        const int half = tid & 1;
        unsigned char tg[24];
#pragma unroll
        for (int e = 0; e < 24; e++) tg[e] = (unsigned char)(half * 24 + e);
        for (int i = 15; i >= 0; i--) {
            const unsigned char* row = bptr + (c * 16 + i) * Kc;
#pragma unroll
            for (int e = 0; e < 24; e++) tg[e] = row[tg[e]];
        }
#pragma unroll
        for (int e = 0; e < 24; e++) Mc[c * Kc + half * 24 + e] = tg[e];
    }
    __syncthreads();
    // Phase B: serial chain over 64 chunks
    if (tid == 0) {
        int tag = *lastp;
        for (int c = 63; c >= 0; c--) {
            Ec[c] = (unsigned char)tag;
            tag = Mc[c * Kc + tag];
        }
    }
    __syncthreads();
    // Phase C: emit 16 path entries per chunk
    if (tid < 64) {
        const int c = tid;
        float* pout = out + 2 * Bc + (size_t)b * Tc + c * 16;
        int tg = Ec[c];
        for (int i = 15; i >= 0; i--) {
            pout[i] = (float)tg;
            tg = bptr[(c * 16 + i) * Kc + tg];
        }
    }
}

extern "C" void kernel_launch(void* const* d_in, const int* in_sizes, int n_in,
                              void* d_out, int out_size)
{
    (void)in_sizes; (void)n_in; (void)out_size;
    const float* feats = (const float*)d_in[0];
    const float* trans = (const float*)d_in[1];
    float* out = (float*)d_out;

    cudaFuncSetAttribute(crf_fused_kernel,
                         cudaFuncAttributeMaxDynamicSharedMemorySize, SMEM_TOTAL);
    crf_fused_kernel<<<Bc, 160, SMEM_TOTAL>>>(feats, trans, out);
}